// round 6
// baseline (speedup 1.0000x reference)
#include <cuda_runtime.h>
#include <cuda_bf16.h>
#include <cstdint>

#define BB   8
#define NP   4096
#define KNN  20
#define CH   64
#define CEPS 1e-5f

// ---------------- scratch (static device globals; no allocation) ----------------
__device__ float g_xx  [BB * NP];
__device__ int   g_idx [BB * NP * KNN];
__device__ float g_A   [BB * CH * NP];
__device__ float g_Bt  [BB * CH * NP];
__device__ float g_Y1  [(size_t)BB * CH * NP * KNN];   // 167.8 MB
__device__ float g_Y2  [(size_t)BB * CH * NP * KNN];   // 167.8 MB
__device__ float g_x1  [BB * CH * NP];
__device__ float g_x2  [BB * CH * NP];
__device__ float g_x3  [BB * CH * NP];
__device__ float g_st  [BB * 1024 * 2];                // mean, rstd per (b, ch)
__device__ float g_Y   [(size_t)BB * 1024 * NP];       // 134 MB
__device__ float g_pool[BB * 1024];

// ---------------- xx = sum_c f^2 ----------------
template<int C>
__global__ void xx_kernel(const float* __restrict__ f, float* __restrict__ xx) {
    int i = blockIdx.x * blockDim.x + threadIdx.x;
    if (i >= BB * NP) return;
    int b = i / NP, n = i % NP;
    const float* fb = f + (size_t)b * C * NP + n;
    float s = 0.f;
#pragma unroll
    for (int c = 0; c < C; c++) { float v = fb[(size_t)c * NP]; s += v * v; }
    xx[i] = s;
}

// ---------------- warp-per-query knn ----------------
// d(m) = 2*<f_n, f_m> - xx[m]  (same ranking as pd; -xx[n] is a per-row const)
// 16 warps per block = 16 queries sharing each candidate tile.
// Each lane scans candidates lane, lane+32, ... keeping a private top-20;
// a 20-step warp head-merge then emits the exact global top-20 indices.
template<int C>
__global__ __launch_bounds__(512)
void knn_warp_kernel(const float* __restrict__ f, const float* __restrict__ xx,
                     int* __restrict__ idxout) {
    constexpr int TQ = 128;
    constexpr int CP = (C == 3) ? 4 : (C + 4);     // padded row stride (bank-conflict-free)
    __shared__ float smc[TQ * CP];
    __shared__ float smxx[TQ];

    int b    = blockIdx.y;
    int warp = threadIdx.x >> 5;
    int lane = threadIdx.x & 31;
    int n    = blockIdx.x * 16 + warp;              // this warp's query
    const float* fb = f + (size_t)b * C * NP;

    float q[C];
#pragma unroll
    for (int c = 0; c < C; c++) q[c] = fb[(size_t)c * NP + n];   // broadcast load

    float vals[KNN];
    int   inds[KNN];
#pragma unroll
    for (int k = 0; k < KNN; k++) { vals[k] = -3.4e38f; inds[k] = 0; }
    float minv = -3.4e38f;

    for (int m0 = 0; m0 < NP; m0 += TQ) {
        __syncthreads();
        for (int i = threadIdx.x; i < TQ * C; i += 512) {
            int c = i / TQ, j = i % TQ;             // coalesced global read over j
            smc[j * CP + c] = fb[(size_t)c * NP + m0 + j];
        }
        if (threadIdx.x < TQ) smxx[threadIdx.x] = xx[b * NP + m0 + threadIdx.x];
        __syncthreads();

#pragma unroll
        for (int jj = 0; jj < TQ / 32; jj++) {
            int j = jj * 32 + lane;
            float d;
            if (C == 3) {
                const float* cj = &smc[j * CP];
                d = 2.f * (q[0] * cj[0] + q[1] * cj[1] + q[2] * cj[2]) - smxx[j];
            } else {
                const float4* cj = (const float4*)&smc[j * CP];
                float d0 = 0.f, d1 = 0.f;
#pragma unroll
                for (int c4 = 0; c4 < C / 8; c4++) {
                    float4 va = cj[2 * c4], vb = cj[2 * c4 + 1];
                    d0 += q[8*c4+0]*va.x + q[8*c4+1]*va.y + q[8*c4+2]*va.z + q[8*c4+3]*va.w;
                    d1 += q[8*c4+4]*vb.x + q[8*c4+5]*vb.y + q[8*c4+6]*vb.z + q[8*c4+7]*vb.w;
                }
                d = 2.f * (d0 + d1) - smxx[j];
            }
            if (d > minv) {
                int p = KNN - 1;
                while (p > 0 && d > vals[p - 1]) {
                    vals[p] = vals[p - 1]; inds[p] = inds[p - 1]; p--;
                }
                vals[p] = d; inds[p] = m0 + j;
                minv = vals[KNN - 1];
            }
        }
    }

    // warp merge: 20 pops of the global max among the 32 sorted lane lists
    int head = 0;
    int* op = idxout + ((size_t)b * NP + n) * KNN;
    for (int k = 0; k < KNN; k++) {
        float h = vals[head];
        float m = h;
#pragma unroll
        for (int off = 16; off; off >>= 1) m = fmaxf(m, __shfl_xor_sync(0xffffffffu, m, off));
        unsigned ball = __ballot_sync(0xffffffffu, h == m);
        if (lane == (__ffs(ball) - 1)) { op[k] = inds[head]; head++; }
    }
}

// ---------------- point transform: A = Wl@f, Bt = (Wr-Wl)@f ----------------
template<int C>
__global__ void pt_kernel(const float* __restrict__ f, const float* __restrict__ Wa,
                          float* __restrict__ A, float* __restrict__ Bt) {
    int i = blockIdx.x * blockDim.x + threadIdx.x;
    if (i >= BB * CH * NP) return;
    int n = i % NP, o = (i / NP) % CH, b = i / (NP * CH);
    const float* fb = f + (size_t)b * C * NP + n;
    const float* w  = Wa + o * 2 * C;
    float a = 0.f, bm = 0.f;
#pragma unroll
    for (int c = 0; c < C; c++) {
        float v = fb[(size_t)c * NP];
        a  += w[c] * v;
        bm += (w[C + c] - w[c]) * v;
    }
    A[i] = a; Bt[i] = bm;
}

// ---------------- y1[bo][n][k] = A[bo][idx[n,k]] + Bt[bo][n] ----------------
__global__ void y1_kernel(const float* __restrict__ A, const float* __restrict__ Bt,
                          const int* __restrict__ idx, float* __restrict__ Y1) {
    __shared__ float sA[NP];                    // 16 KB: full A plane for this (b,o)
    int bo = blockIdx.y;
    int b  = bo / CH;
    for (int i = threadIdx.x; i < NP; i += blockDim.x)
        sA[i] = A[(size_t)bo * NP + i];
    __syncthreads();
    int n0 = blockIdx.x * 512;
    const int*  ib = idx + ((size_t)b * NP + n0) * KNN;
    const float* bt = Bt + (size_t)bo * NP + n0;
    float* y = Y1 + ((size_t)bo * NP + n0) * KNN;
    for (int i = threadIdx.x; i < 512 * KNN; i += blockDim.x) {
        int nl = i / KNN;
        y[i] = sA[ib[i]] + bt[nl];
    }
}

// ---------------- per-channel mean / rstd (fp32, vectorized, one block/channel) ----------------
__global__ __launch_bounds__(256)
void stats_kernel(const float* __restrict__ src, float* __restrict__ stats, int P) {
    int ch = blockIdx.x;
    const float4* p = (const float4*)(src + (size_t)ch * P);
    int P4 = P >> 2;
    float sx = 0.f, sy = 0.f, sz = 0.f, sw = 0.f;
    float qx = 0.f, qy = 0.f, qz = 0.f, qw = 0.f;
    for (int i = threadIdx.x; i < P4; i += 256) {
        float4 v = p[i];
        sx += v.x; sy += v.y; sz += v.z; sw += v.w;
        qx += v.x * v.x; qy += v.y * v.y; qz += v.z * v.z; qw += v.w * v.w;
    }
    float s  = (sx + sy) + (sz + sw);
    float s2 = (qx + qy) + (qz + qw);
    __shared__ float sh[512];
    sh[threadIdx.x] = s; sh[256 + threadIdx.x] = s2;
    __syncthreads();
    for (int st = 128; st > 0; st >>= 1) {
        if (threadIdx.x < st) {
            sh[threadIdx.x]       += sh[threadIdx.x + st];
            sh[256 + threadIdx.x] += sh[256 + threadIdx.x + st];
        }
        __syncthreads();
    }
    if (threadIdx.x == 0) {
        float m   = sh[0] / (float)P;
        float var = sh[256] / (float)P - m * m;
        stats[ch * 2]     = m;
        stats[ch * 2 + 1] = rsqrtf(var + CEPS);
    }
}

// ---------------- conv2: y2 = Wb @ lrelu(inorm(y1)), 2 points/thread ----------------
__global__ __launch_bounds__(128)
void conv2_kernel(const float* __restrict__ Y1, const float* __restrict__ Wb,
                  const float* __restrict__ stats, float* __restrict__ Y2) {
    const int P = NP * KNN;
    __shared__ float sWt[CH * CH];      // transposed: [c][o]
    __shared__ float sm[CH], sr[CH];
    int b = blockIdx.y;
    for (int i = threadIdx.x; i < CH * CH; i += 128) {
        int c = i >> 6, o = i & 63;
        sWt[c * CH + o] = Wb[o * CH + c];
    }
    if (threadIdx.x < CH) {
        sm[threadIdx.x] = stats[(b * CH + threadIdx.x) * 2];
        sr[threadIdx.x] = stats[(b * CH + threadIdx.x) * 2 + 1];
    }
    __syncthreads();
    int p0 = blockIdx.x * 256 + threadIdx.x;
    int p1 = p0 + 128;
    float acc0[CH], acc1[CH];
#pragma unroll
    for (int o = 0; o < CH; o++) { acc0[o] = 0.f; acc1[o] = 0.f; }
    const float* y1 = Y1 + (size_t)b * CH * P;
#pragma unroll 2
    for (int c = 0; c < CH; c++) {
        float v0 = y1[(size_t)c * P + p0];
        float v1 = y1[(size_t)c * P + p1];
        float m = sm[c], r = sr[c];
        v0 = (v0 - m) * r; v0 = v0 > 0.f ? v0 : 0.2f * v0;
        v1 = (v1 - m) * r; v1 = v1 > 0.f ? v1 : 0.2f * v1;
        const float4* w = (const float4*)&sWt[c * CH];
#pragma unroll
        for (int o4 = 0; o4 < 16; o4++) {
            float4 w4 = w[o4];
            acc0[4*o4+0] += w4.x * v0; acc1[4*o4+0] += w4.x * v1;
            acc0[4*o4+1] += w4.y * v0; acc1[4*o4+1] += w4.y * v1;
            acc0[4*o4+2] += w4.z * v0; acc1[4*o4+2] += w4.z * v1;
            acc0[4*o4+3] += w4.w * v0; acc1[4*o4+3] += w4.w * v1;
        }
    }
    float* y2 = Y2 + (size_t)b * CH * P;
#pragma unroll
    for (int o = 0; o < CH; o++) {
        y2[(size_t)o * P + p0] = acc0[o];
        y2[(size_t)o * P + p1] = acc1[o];
    }
}

// ---------------- max over K of lrelu(inorm(y2)) ----------------
__global__ void maxk_kernel(const float* __restrict__ Y2, const float* __restrict__ stats,
                            float* __restrict__ xout) {
    int i = blockIdx.x * blockDim.x + threadIdx.x;   // over B*CH*NP
    if (i >= BB * CH * NP) return;
    int bo = i / NP;
    float m = stats[bo * 2], r = stats[bo * 2 + 1];
    const float4* y = (const float4*)(Y2 + (size_t)i * KNN);
    float mx = -3.4e38f;
#pragma unroll
    for (int k4 = 0; k4 < 5; k4++) {
        float4 v = y[k4];
        mx = fmaxf(mx, fmaxf(fmaxf(v.x, v.y), fmaxf(v.z, v.w)));
    }
    float v = (mx - m) * r;          // max commutes with the monotone affine map (r>0)
    v = v > 0.f ? v : 0.2f * v;
    xout[i] = v;
}

// ---------------- final GEMM: Y[b, o, n] = Ws[o, :] @ concat(x1,x2,x3)[b, :, n] ----------------
__global__ __launch_bounds__(128)
void fgemm_kernel(const float* __restrict__ x1, const float* __restrict__ x2,
                  const float* __restrict__ x3, const float* __restrict__ Ws,
                  float* __restrict__ Y) {
    __shared__ float sWt[192 * 64];                // transposed [c][o], 48 KB
    int b  = blockIdx.z;
    int o0 = blockIdx.y * 64;
    int n0 = blockIdx.x * 256 + threadIdx.x;
    int n1 = n0 + 128;
    for (int i = threadIdx.x; i < 192 * 64; i += 128) {
        int c = i >> 6, o = i & 63;
        sWt[c * 64 + o] = Ws[(size_t)(o0 + o) * 192 + c];
    }
    __syncthreads();
    float acc0[64], acc1[64];
#pragma unroll
    for (int o = 0; o < 64; o++) { acc0[o] = 0.f; acc1[o] = 0.f; }
    const float* srcs[3] = { x1 + (size_t)b * CH * NP,
                             x2 + (size_t)b * CH * NP,
                             x3 + (size_t)b * CH * NP };
    for (int g = 0; g < 3; g++) {
        const float* s = srcs[g];
#pragma unroll 2
        for (int c = 0; c < 64; c++) {
            float v0 = s[(size_t)c * NP + n0];
            float v1 = s[(size_t)c * NP + n1];
            const float4* w = (const float4*)&sWt[(g * 64 + c) * 64];
#pragma unroll
            for (int o4 = 0; o4 < 16; o4++) {
                float4 w4 = w[o4];
                acc0[4*o4+0] += w4.x * v0; acc1[4*o4+0] += w4.x * v1;
                acc0[4*o4+1] += w4.y * v0; acc1[4*o4+1] += w4.y * v1;
                acc0[4*o4+2] += w4.z * v0; acc1[4*o4+2] += w4.z * v1;
                acc0[4*o4+3] += w4.w * v0; acc1[4*o4+3] += w4.w * v1;
            }
        }
    }
    float* y = Y + ((size_t)b * 1024 + o0) * NP;
#pragma unroll
    for (int o = 0; o < 64; o++) {
        y[(size_t)o * NP + n0] = acc0[o];
        y[(size_t)o * NP + n1] = acc1[o];
    }
}

// ---------------- global max pool of lrelu(inorm(Y)) ----------------
__global__ void pool_kernel(const float* __restrict__ Y, const float* __restrict__ stats,
                            float* __restrict__ pool) {
    int ch = blockIdx.x;            // b*1024 + o
    float m = stats[ch * 2], r = stats[ch * 2 + 1];
    const float4* y = (const float4*)(Y + (size_t)ch * NP);
    float mx = -3.4e38f;
    for (int i = threadIdx.x; i < NP / 4; i += 128) {
        float4 v = y[i];
        mx = fmaxf(mx, fmaxf(fmaxf(v.x, v.y), fmaxf(v.z, v.w)));
    }
    __shared__ float sh[128];
    sh[threadIdx.x] = mx; __syncthreads();
    for (int st = 64; st > 0; st >>= 1) {
        if (threadIdx.x < st) sh[threadIdx.x] = fmaxf(sh[threadIdx.x], sh[threadIdx.x + st]);
        __syncthreads();
    }
    if (threadIdx.x == 0) {
        float v = (sh[0] - m) * r;   // max commutes with monotone affine map (r>0)
        v = v > 0.f ? v : 0.2f * v;
        pool[ch] = v;
    }
}

// ---------------- assemble output: [pool bcast | x1 | x2 | x3] ----------------
__global__ void out_kernel(const float* __restrict__ pool, const float* __restrict__ x1,
                           const float* __restrict__ x2, const float* __restrict__ x3,
                           float* __restrict__ out) {
    size_t i = (size_t)blockIdx.x * blockDim.x + threadIdx.x;
    const size_t total = (size_t)BB * 1216 * NP;
    if (i >= total) return;
    int n  = (int)(i % NP);
    int ch = (int)((i / NP) % 1216);
    int b  = (int)(i / ((size_t)NP * 1216));
    float v;
    if (ch < 1024) {
        v = pool[b * 1024 + ch];
    } else {
        int c2 = ch - 1024;
        const float* s = (c2 < 64) ? x1 : (c2 < 128 ? x2 : x3);
        v = s[((size_t)b * CH + (c2 & 63)) * NP + n];
    }
    out[i] = v;
}

// ---------------- orchestration ----------------
template<int C>
static void run_edge_layer(const float* f, const float* Wa, const float* Wb, float* xout,
                           float* xxp, int* idxp, float* Ap, float* Btp,
                           float* Y1p, float* Y2p, float* stp) {
    xx_kernel<C><<<(BB * NP + 255) / 256, 256>>>(f, xxp);
    knn_warp_kernel<C><<<dim3(NP / 16, BB), 512>>>(f, xxp, idxp);
    pt_kernel<C><<<(BB * CH * NP + 255) / 256, 256>>>(f, Wa, Ap, Btp);
    y1_kernel<<<dim3(NP / 512, BB * CH), 256>>>(Ap, Btp, idxp, Y1p);
    stats_kernel<<<BB * CH, 256>>>(Y1p, stp, NP * KNN);
    conv2_kernel<<<dim3(NP * KNN / 256, BB), 128>>>(Y1p, Wb, stp, Y2p);
    stats_kernel<<<BB * CH, 256>>>(Y2p, stp, NP * KNN);
    maxk_kernel<<<(BB * CH * NP + 255) / 256, 256>>>(Y2p, stp, xout);
}

extern "C" void kernel_launch(void* const* d_in, const int* in_sizes, int n_in,
                              void* d_out, int out_size) {
    const float* x   = (const float*)d_in[0];
    const float* W0a = (const float*)d_in[1];
    const float* W0b = (const float*)d_in[2];
    const float* W1a = (const float*)d_in[3];
    const float* W1b = (const float*)d_in[4];
    const float* W2a = (const float*)d_in[5];
    const float* W2b = (const float*)d_in[6];
    const float* Ws  = (const float*)d_in[7];
    float* out = (float*)d_out;

    float *xxp, *Ap, *Btp, *Y1p, *Y2p, *x1p, *x2p, *x3p, *stp, *Yp, *poolp;
    int* idxp;
    cudaGetSymbolAddress((void**)&xxp,   g_xx);
    cudaGetSymbolAddress((void**)&idxp,  g_idx);
    cudaGetSymbolAddress((void**)&Ap,    g_A);
    cudaGetSymbolAddress((void**)&Btp,   g_Bt);
    cudaGetSymbolAddress((void**)&Y1p,   g_Y1);
    cudaGetSymbolAddress((void**)&Y2p,   g_Y2);
    cudaGetSymbolAddress((void**)&x1p,   g_x1);
    cudaGetSymbolAddress((void**)&x2p,   g_x2);
    cudaGetSymbolAddress((void**)&x3p,   g_x3);
    cudaGetSymbolAddress((void**)&stp,   g_st);
    cudaGetSymbolAddress((void**)&Yp,    g_Y);
    cudaGetSymbolAddress((void**)&poolp, g_pool);

    run_edge_layer<3> (x,   W0a, W0b, x1p, xxp, idxp, Ap, Btp, Y1p, Y2p, stp);
    run_edge_layer<CH>(x1p, W1a, W1b, x2p, xxp, idxp, Ap, Btp, Y1p, Y2p, stp);
    run_edge_layer<CH>(x2p, W2a, W2b, x3p, xxp, idxp, Ap, Btp, Y1p, Y2p, stp);

    fgemm_kernel<<<dim3(NP / 256, 1024 / 64, BB), 128>>>(x1p, x2p, x3p, Ws, Yp);
    stats_kernel<<<BB * 1024, 256>>>(Yp, stp, NP);
    pool_kernel<<<BB * 1024, 128>>>(Yp, stp, poolp);

    const size_t total = (size_t)BB * 1216 * NP;
    out_kernel<<<(unsigned)((total + 255) / 256), 256>>>(poolp, x1p, x2p, x3p, out);
}

// round 8
// speedup vs baseline: 4.2439x; 4.2439x over previous
#include <cuda_runtime.h>
#include <cuda_bf16.h>
#include <cstdint>

#define BB   8
#define NP   4096
#define KNN  20
#define CH   64
#define CEPS 1e-5f

// ---------------- scratch (static device globals; no allocation) ----------------
__device__ float g_xx  [BB * NP];
__device__ int   g_idx [BB * NP * KNN];
__device__ float g_A   [BB * CH * NP];
__device__ float g_Bt  [BB * CH * NP];
__device__ float g_Y1  [(size_t)BB * CH * NP * KNN];   // 167.8 MB
__device__ float g_Y2  [(size_t)BB * CH * NP * KNN];   // 167.8 MB
__device__ float g_x1  [BB * CH * NP];
__device__ float g_x2  [BB * CH * NP];
__device__ float g_x3  [BB * CH * NP];
__device__ float g_st  [BB * 1024 * 2];                // mean, rstd per (b, ch)
__device__ float g_Y   [(size_t)BB * 1024 * NP];       // 134 MB
__device__ float g_pool[BB * 1024];

// ---------------- xx = sum_c f^2 ----------------
template<int C>
__global__ void xx_kernel(const float* __restrict__ f, float* __restrict__ xx) {
    int i = blockIdx.x * blockDim.x + threadIdx.x;
    if (i >= BB * NP) return;
    int b = i / NP, n = i % NP;
    const float* fb = f + (size_t)b * C * NP + n;
    float s = 0.f;
#pragma unroll
    for (int c = 0; c < C; c++) { float v = fb[(size_t)c * NP]; s += v * v; }
    xx[i] = s;
}

// ---------------- thread-per-query knn, register-resident branch-free top-K ----------------
// d(m) = 2*<f_n, f_m> - xx[m]  (same ranking as pd; -xx[n] is a per-row const).
// vals/inds fully unrolled -> registers. Strict '>' + ascending scan keeps
// lowest-index-first tie order (matches lax.top_k).
template<int C>
__global__ __launch_bounds__(128)
void knn_kernel(const float* __restrict__ f, const float* __restrict__ xx,
                int* __restrict__ idxout) {
    const int TQ = 128;
    constexpr int CP = (C == 3) ? 4 : (C + 4);   // padded row stride: 16B-aligned, low STS conflicts
    __shared__ float smc[TQ * CP];
    __shared__ float smxx[TQ];
    int b = blockIdx.y;
    int n = blockIdx.x * TQ + threadIdx.x;
    const float* fb = f + (size_t)b * C * NP;

    float q[C];
#pragma unroll
    for (int c = 0; c < C; c++) q[c] = fb[(size_t)c * NP + n];

    float vals[KNN];
    int   inds[KNN];
#pragma unroll
    for (int k = 0; k < KNN; k++) { vals[k] = -3.4e38f; inds[k] = 0; }
    float minv = -3.4e38f;

    for (int m0 = 0; m0 < NP; m0 += TQ) {
        __syncthreads();
        for (int i = threadIdx.x; i < TQ * C; i += TQ) {
            int c = i / TQ, j = i % TQ;               // coalesced global read over j
            smc[j * CP + c] = fb[(size_t)c * NP + m0 + j];
        }
        smxx[threadIdx.x] = xx[b * NP + m0 + threadIdx.x];
        __syncthreads();

        for (int j = 0; j < TQ; j += 2) {
            float d0, d1;
            if (C == 3) {
                const float* c0 = &smc[j * CP];
                const float* c1 = &smc[(j + 1) * CP];
                d0 = 2.f * (q[0]*c0[0] + q[1]*c0[1] + q[2]*c0[2]) - smxx[j];
                d1 = 2.f * (q[0]*c1[0] + q[1]*c1[1] + q[2]*c1[2]) - smxx[j + 1];
            } else {
                const float4* c0 = (const float4*)&smc[j * CP];        // broadcast LDS.128
                const float4* c1 = (const float4*)&smc[(j + 1) * CP];
                float a0=0.f,a1=0.f,a2=0.f,a3=0.f, e0=0.f,e1=0.f,e2=0.f,e3=0.f;
#pragma unroll
                for (int c4 = 0; c4 < C / 4; c4++) {
                    float4 v0 = c0[c4], v1 = c1[c4];
                    a0 += q[4*c4+0]*v0.x; a1 += q[4*c4+1]*v0.y;
                    a2 += q[4*c4+2]*v0.z; a3 += q[4*c4+3]*v0.w;
                    e0 += q[4*c4+0]*v1.x; e1 += q[4*c4+1]*v1.y;
                    e2 += q[4*c4+2]*v1.z; e3 += q[4*c4+3]*v1.w;
                }
                d0 = 2.f * ((a0 + a1) + (a2 + a3)) - smxx[j];
                d1 = 2.f * ((e0 + e1) + (e2 + e3)) - smxx[j + 1];
            }
            if (d0 > minv) {                          // branch-free register bubble insert
                float v = d0; int id = m0 + j;
#pragma unroll
                for (int k = 0; k < KNN; k++) {
                    if (v > vals[k]) {
                        float tv = vals[k]; vals[k] = v; v = tv;
                        int   ti = inds[k]; inds[k] = id; id = ti;
                    }
                }
                minv = vals[KNN - 1];
            }
            if (d1 > minv) {
                float v = d1; int id = m0 + j + 1;
#pragma unroll
                for (int k = 0; k < KNN; k++) {
                    if (v > vals[k]) {
                        float tv = vals[k]; vals[k] = v; v = tv;
                        int   ti = inds[k]; inds[k] = id; id = ti;
                    }
                }
                minv = vals[KNN - 1];
            }
        }
    }
    int* op = idxout + ((size_t)b * NP + n) * KNN;
#pragma unroll
    for (int k = 0; k < KNN; k++) op[k] = inds[k];
}

// ---------------- point transform: A = Wl@f, Bt = (Wr-Wl)@f ----------------
template<int C>
__global__ void pt_kernel(const float* __restrict__ f, const float* __restrict__ Wa,
                          float* __restrict__ A, float* __restrict__ Bt) {
    int i = blockIdx.x * blockDim.x + threadIdx.x;
    if (i >= BB * CH * NP) return;
    int n = i % NP, o = (i / NP) % CH, b = i / (NP * CH);
    const float* fb = f + (size_t)b * C * NP + n;
    const float* w  = Wa + o * 2 * C;
    float a = 0.f, bm = 0.f;
#pragma unroll
    for (int c = 0; c < C; c++) {
        float v = fb[(size_t)c * NP];
        a  += w[c] * v;
        bm += (w[C + c] - w[c]) * v;
    }
    A[i] = a; Bt[i] = bm;
}

// ---------------- y1[bo][n][k] = A[bo][idx[n,k]] + Bt[bo][n] ----------------
__global__ void y1_kernel(const float* __restrict__ A, const float* __restrict__ Bt,
                          const int* __restrict__ idx, float* __restrict__ Y1) {
    __shared__ float sA[NP];                    // 16 KB: full A plane for this (b,o)
    int bo = blockIdx.y;
    int b  = bo / CH;
    for (int i = threadIdx.x; i < NP; i += blockDim.x)
        sA[i] = A[(size_t)bo * NP + i];
    __syncthreads();
    int n0 = blockIdx.x * 512;
    const int*  ib = idx + ((size_t)b * NP + n0) * KNN;
    const float* bt = Bt + (size_t)bo * NP + n0;
    float* y = Y1 + ((size_t)bo * NP + n0) * KNN;
    for (int i = threadIdx.x; i < 512 * KNN; i += blockDim.x) {
        int nl = i / KNN;
        y[i] = sA[ib[i]] + bt[nl];
    }
}

// ---------------- per-channel mean / rstd (fp32, vectorized, one block/channel) ----------------
__global__ __launch_bounds__(256)
void stats_kernel(const float* __restrict__ src, float* __restrict__ stats, int P) {
    int ch = blockIdx.x;
    const float4* p = (const float4*)(src + (size_t)ch * P);
    int P4 = P >> 2;
    float sx = 0.f, sy = 0.f, sz = 0.f, sw = 0.f;
    float qx = 0.f, qy = 0.f, qz = 0.f, qw = 0.f;
    for (int i = threadIdx.x; i < P4; i += 256) {
        float4 v = p[i];
        sx += v.x; sy += v.y; sz += v.z; sw += v.w;
        qx += v.x * v.x; qy += v.y * v.y; qz += v.z * v.z; qw += v.w * v.w;
    }
    float s  = (sx + sy) + (sz + sw);
    float s2 = (qx + qy) + (qz + qw);
    __shared__ float sh[512];
    sh[threadIdx.x] = s; sh[256 + threadIdx.x] = s2;
    __syncthreads();
    for (int st = 128; st > 0; st >>= 1) {
        if (threadIdx.x < st) {
            sh[threadIdx.x]       += sh[threadIdx.x + st];
            sh[256 + threadIdx.x] += sh[256 + threadIdx.x + st];
        }
        __syncthreads();
    }
    if (threadIdx.x == 0) {
        float m   = sh[0] / (float)P;
        float var = sh[256] / (float)P - m * m;
        stats[ch * 2]     = m;
        stats[ch * 2 + 1] = rsqrtf(var + CEPS);
    }
}

// ---------------- conv2: y2 = Wb @ lrelu(inorm(y1)), 2 points/thread ----------------
__global__ __launch_bounds__(128)
void conv2_kernel(const float* __restrict__ Y1, const float* __restrict__ Wb,
                  const float* __restrict__ stats, float* __restrict__ Y2) {
    const int P = NP * KNN;
    __shared__ float sWt[CH * CH];      // transposed: [c][o]
    __shared__ float sm[CH], sr[CH];
    int b = blockIdx.y;
    for (int i = threadIdx.x; i < CH * CH; i += 128) {
        int c = i >> 6, o = i & 63;
        sWt[c * CH + o] = Wb[o * CH + c];
    }
    if (threadIdx.x < CH) {
        sm[threadIdx.x] = stats[(b * CH + threadIdx.x) * 2];
        sr[threadIdx.x] = stats[(b * CH + threadIdx.x) * 2 + 1];
    }
    __syncthreads();
    int p0 = blockIdx.x * 256 + threadIdx.x;
    int p1 = p0 + 128;
    float acc0[CH], acc1[CH];
#pragma unroll
    for (int o = 0; o < CH; o++) { acc0[o] = 0.f; acc1[o] = 0.f; }
    const float* y1 = Y1 + (size_t)b * CH * P;
#pragma unroll 2
    for (int c = 0; c < CH; c++) {
        float v0 = y1[(size_t)c * P + p0];
        float v1 = y1[(size_t)c * P + p1];
        float m = sm[c], r = sr[c];
        v0 = (v0 - m) * r; v0 = v0 > 0.f ? v0 : 0.2f * v0;
        v1 = (v1 - m) * r; v1 = v1 > 0.f ? v1 : 0.2f * v1;
        const float4* w = (const float4*)&sWt[c * CH];
#pragma unroll
        for (int o4 = 0; o4 < 16; o4++) {
            float4 w4 = w[o4];
            acc0[4*o4+0] += w4.x * v0; acc1[4*o4+0] += w4.x * v1;
            acc0[4*o4+1] += w4.y * v0; acc1[4*o4+1] += w4.y * v1;
            acc0[4*o4+2] += w4.z * v0; acc1[4*o4+2] += w4.z * v1;
            acc0[4*o4+3] += w4.w * v0; acc1[4*o4+3] += w4.w * v1;
        }
    }
    float* y2 = Y2 + (size_t)b * CH * P;
#pragma unroll
    for (int o = 0; o < CH; o++) {
        y2[(size_t)o * P + p0] = acc0[o];
        y2[(size_t)o * P + p1] = acc1[o];
    }
}

// ---------------- max over K of lrelu(inorm(y2)) ----------------
__global__ void maxk_kernel(const float* __restrict__ Y2, const float* __restrict__ stats,
                            float* __restrict__ xout) {
    int i = blockIdx.x * blockDim.x + threadIdx.x;   // over B*CH*NP
    if (i >= BB * CH * NP) return;
    int bo = i / NP;
    float m = stats[bo * 2], r = stats[bo * 2 + 1];
    const float4* y = (const float4*)(Y2 + (size_t)i * KNN);
    float mx = -3.4e38f;
#pragma unroll
    for (int k4 = 0; k4 < 5; k4++) {
        float4 v = y[k4];
        mx = fmaxf(mx, fmaxf(fmaxf(v.x, v.y), fmaxf(v.z, v.w)));
    }
    float v = (mx - m) * r;          // max commutes with the monotone affine map (r>0)
    v = v > 0.f ? v : 0.2f * v;
    xout[i] = v;
}

// ---------------- final GEMM: Y[b, o, n] = Ws[o, :] @ concat(x1,x2,x3)[b, :, n] ----------------
__global__ __launch_bounds__(128)
void fgemm_kernel(const float* __restrict__ x1, const float* __restrict__ x2,
                  const float* __restrict__ x3, const float* __restrict__ Ws,
                  float* __restrict__ Y) {
    __shared__ float sWt[192 * 64];                // transposed [c][o], 48 KB
    int b  = blockIdx.z;
    int o0 = blockIdx.y * 64;
    int n0 = blockIdx.x * 256 + threadIdx.x;
    int n1 = n0 + 128;
    for (int i = threadIdx.x; i < 192 * 64; i += 128) {
        int c = i >> 6, o = i & 63;
        sWt[c * 64 + o] = Ws[(size_t)(o0 + o) * 192 + c];
    }
    __syncthreads();
    float acc0[64], acc1[64];
#pragma unroll
    for (int o = 0; o < 64; o++) { acc0[o] = 0.f; acc1[o] = 0.f; }
    const float* srcs[3] = { x1 + (size_t)b * CH * NP,
                             x2 + (size_t)b * CH * NP,
                             x3 + (size_t)b * CH * NP };
    for (int g = 0; g < 3; g++) {
        const float* s = srcs[g];
#pragma unroll 2
        for (int c = 0; c < 64; c++) {
            float v0 = s[(size_t)c * NP + n0];
            float v1 = s[(size_t)c * NP + n1];
            const float4* w = (const float4*)&sWt[(g * 64 + c) * 64];
#pragma unroll
            for (int o4 = 0; o4 < 16; o4++) {
                float4 w4 = w[o4];
                acc0[4*o4+0] += w4.x * v0; acc1[4*o4+0] += w4.x * v1;
                acc0[4*o4+1] += w4.y * v0; acc1[4*o4+1] += w4.y * v1;
                acc0[4*o4+2] += w4.z * v0; acc1[4*o4+2] += w4.z * v1;
                acc0[4*o4+3] += w4.w * v0; acc1[4*o4+3] += w4.w * v1;
            }
        }
    }
    float* y = Y + ((size_t)b * 1024 + o0) * NP;
#pragma unroll
    for (int o = 0; o < 64; o++) {
        y[(size_t)o * NP + n0] = acc0[o];
        y[(size_t)o * NP + n1] = acc1[o];
    }
}

// ---------------- global max pool of lrelu(inorm(Y)) ----------------
__global__ void pool_kernel(const float* __restrict__ Y, const float* __restrict__ stats,
                            float* __restrict__ pool) {
    int ch = blockIdx.x;            // b*1024 + o
    float m = stats[ch * 2], r = stats[ch * 2 + 1];
    const float4* y = (const float4*)(Y + (size_t)ch * NP);
    float mx = -3.4e38f;
    for (int i = threadIdx.x; i < NP / 4; i += 128) {
        float4 v = y[i];
        mx = fmaxf(mx, fmaxf(fmaxf(v.x, v.y), fmaxf(v.z, v.w)));
    }
    __shared__ float sh[128];
    sh[threadIdx.x] = mx; __syncthreads();
    for (int st = 64; st > 0; st >>= 1) {
        if (threadIdx.x < st) sh[threadIdx.x] = fmaxf(sh[threadIdx.x], sh[threadIdx.x + st]);
        __syncthreads();
    }
    if (threadIdx.x == 0) {
        float v = (sh[0] - m) * r;   // max commutes with monotone affine map (r>0)
        v = v > 0.f ? v : 0.2f * v;
        pool[ch] = v;
    }
}

// ---------------- assemble output: [pool bcast | x1 | x2 | x3] ----------------
__global__ void out_kernel(const float* __restrict__ pool, const float* __restrict__ x1,
                           const float* __restrict__ x2, const float* __restrict__ x3,
                           float* __restrict__ out) {
    size_t i = (size_t)blockIdx.x * blockDim.x + threadIdx.x;
    const size_t total = (size_t)BB * 1216 * NP;
    if (i >= total) return;
    int n  = (int)(i % NP);
    int ch = (int)((i / NP) % 1216);
    int b  = (int)(i / ((size_t)NP * 1216));
    float v;
    if (ch < 1024) {
        v = pool[b * 1024 + ch];
    } else {
        int c2 = ch - 1024;
        const float* s = (c2 < 64) ? x1 : (c2 < 128 ? x2 : x3);
        v = s[((size_t)b * CH + (c2 & 63)) * NP + n];
    }
    out[i] = v;
}

// ---------------- orchestration ----------------
template<int C>
static void run_edge_layer(const float* f, const float* Wa, const float* Wb, float* xout,
                           float* xxp, int* idxp, float* Ap, float* Btp,
                           float* Y1p, float* Y2p, float* stp) {
    xx_kernel<C><<<(BB * NP + 255) / 256, 256>>>(f, xxp);
    knn_kernel<C><<<dim3(NP / 128, BB), 128>>>(f, xxp, idxp);
    pt_kernel<C><<<(BB * CH * NP + 255) / 256, 256>>>(f, Wa, Ap, Btp);
    y1_kernel<<<dim3(NP / 512, BB * CH), 256>>>(Ap, Btp, idxp, Y1p);
    stats_kernel<<<BB * CH, 256>>>(Y1p, stp, NP * KNN);
    conv2_kernel<<<dim3(NP * KNN / 256, BB), 128>>>(Y1p, Wb, stp, Y2p);
    stats_kernel<<<BB * CH, 256>>>(Y2p, stp, NP * KNN);
    maxk_kernel<<<(BB * CH * NP + 255) / 256, 256>>>(Y2p, stp, xout);
}

extern "C" void kernel_launch(void* const* d_in, const int* in_sizes, int n_in,
                              void* d_out, int out_size) {
    const float* x   = (const float*)d_in[0];
    const float* W0a = (const float*)d_in[1];
    const float* W0b = (const float*)d_in[2];
    const float* W1a = (const float*)d_in[3];
    const float* W1b = (const float*)d_in[4];
    const float* W2a = (const float*)d_in[5];
    const float* W2b = (const float*)d_in[6];
    const float* Ws  = (const float*)d_in[7];
    float* out = (float*)d_out;

    float *xxp, *Ap, *Btp, *Y1p, *Y2p, *x1p, *x2p, *x3p, *stp, *Yp, *poolp;
    int* idxp;
    cudaGetSymbolAddress((void**)&xxp,   g_xx);
    cudaGetSymbolAddress((void**)&idxp,  g_idx);
    cudaGetSymbolAddress((void**)&Ap,    g_A);
    cudaGetSymbolAddress((void**)&Btp,   g_Bt);
    cudaGetSymbolAddress((void**)&Y1p,   g_Y1);
    cudaGetSymbolAddress((void**)&Y2p,   g_Y2);
    cudaGetSymbolAddress((void**)&x1p,   g_x1);
    cudaGetSymbolAddress((void**)&x2p,   g_x2);
    cudaGetSymbolAddress((void**)&x3p,   g_x3);
    cudaGetSymbolAddress((void**)&stp,   g_st);
    cudaGetSymbolAddress((void**)&Yp,    g_Y);
    cudaGetSymbolAddress((void**)&poolp, g_pool);

    run_edge_layer<3> (x,   W0a, W0b, x1p, xxp, idxp, Ap, Btp, Y1p, Y2p, stp);
    run_edge_layer<CH>(x1p, W1a, W1b, x2p, xxp, idxp, Ap, Btp, Y1p, Y2p, stp);
    run_edge_layer<CH>(x2p, W2a, W2b, x3p, xxp, idxp, Ap, Btp, Y1p, Y2p, stp);

    fgemm_kernel<<<dim3(NP / 256, 1024 / 64, BB), 128>>>(x1p, x2p, x3p, Ws, Yp);
    stats_kernel<<<BB * 1024, 256>>>(Yp, stp, NP);
    pool_kernel<<<BB * 1024, 128>>>(Yp, stp, poolp);

    const size_t total = (size_t)BB * 1216 * NP;
    out_kernel<<<(unsigned)((total + 255) / 256), 256>>>(poolp, x1p, x2p, x3p, out);
}

// round 9
// speedup vs baseline: 4.9046x; 1.1557x over previous
#include <cuda_runtime.h>
#include <cuda_bf16.h>
#include <cstdint>

#define BB   8
#define NP   4096
#define KNN  20
#define CH   64
#define CEPS 1e-5f

// ---------------- scratch (static device globals; no allocation) ----------------
__device__ float g_xx  [BB * NP];
__device__ int   g_idxA[BB * NP * KNN];
__device__ int   g_idxB[BB * NP * KNN];
__device__ float g_ft  [BB * NP * CH];                 // transposed features [b][n][c]
__device__ float g_A   [BB * CH * NP];
__device__ float g_Bt  [BB * CH * NP];
__device__ float g_Y1  [(size_t)BB * CH * NP * KNN];   // 167.8 MB
__device__ float g_Y2  [(size_t)BB * CH * NP * KNN];   // 167.8 MB
__device__ float g_x1  [BB * CH * NP];
__device__ float g_x2  [BB * CH * NP];
__device__ float g_x3  [BB * CH * NP];
__device__ float g_st  [BB * 1024 * 2];                // mean, rstd per (b, ch)
__device__ float g_Y   [(size_t)BB * 1024 * NP];       // 134 MB
__device__ float g_pool[BB * 1024];

// ---------------- packed f32x2 helpers ----------------
#define FMA_F32X2(d, a, b, c) \
    asm("fma.rn.f32x2 %0, %1, %2, %3;" : "=l"(d) : "l"(a), "l"(b), "l"(c))

__device__ __forceinline__ float f32x2_hsum(unsigned long long v) {
    float lo, hi;
    asm("mov.b64 {%0, %1}, %2;" : "=f"(lo), "=f"(hi) : "l"(v));
    return lo + hi;
}

// ---------------- xx = sum_c f^2 ----------------
template<int C>
__global__ void xx_kernel(const float* __restrict__ f, float* __restrict__ xx) {
    int i = blockIdx.x * blockDim.x + threadIdx.x;
    if (i >= BB * NP) return;
    int b = i / NP, n = i % NP;
    const float* fb = f + (size_t)b * C * NP + n;
    float s = 0.f;
#pragma unroll
    for (int c = 0; c < C; c++) { float v = fb[(size_t)c * NP]; s += v * v; }
    xx[i] = s;
}

// ---------------- transpose: f[b][c][n] -> ft[b][n][c] ----------------
__global__ void transpose_kernel(const float* __restrict__ f, float* __restrict__ ft) {
    __shared__ float t[32][33];
    int b  = blockIdx.z;
    int c0 = blockIdx.y * 32;
    int n0 = blockIdx.x * 32;
    int tx = threadIdx.x, ty = threadIdx.y;
#pragma unroll
    for (int dy = 0; dy < 32; dy += 8)
        t[ty + dy][tx] = f[(size_t)b * CH * NP + (size_t)(c0 + ty + dy) * NP + n0 + tx];
    __syncthreads();
#pragma unroll
    for (int dy = 0; dy < 32; dy += 8)
        ft[(size_t)b * NP * CH + (size_t)(n0 + ty + dy) * CH + c0 + tx] = t[tx][ty + dy];
}

// ---------------- C=3 knn (round-8 proven path) ----------------
__global__ __launch_bounds__(128)
void knn3_kernel(const float* __restrict__ f, const float* __restrict__ xx,
                 int* __restrict__ idxout) {
    const int TQ = 128;
    const int CP = 4;
    __shared__ float smc[TQ * CP];
    __shared__ float smxx[TQ];
    int b = blockIdx.y;
    int n = blockIdx.x * TQ + threadIdx.x;
    const float* fb = f + (size_t)b * 3 * NP;

    float q0 = fb[n], q1 = fb[NP + n], q2 = fb[2 * NP + n];

    float vals[KNN];
    int   inds[KNN];
#pragma unroll
    for (int k = 0; k < KNN; k++) { vals[k] = -3.4e38f; inds[k] = 0; }
    float minv = -3.4e38f;

    for (int m0 = 0; m0 < NP; m0 += TQ) {
        __syncthreads();
        for (int i = threadIdx.x; i < TQ * 3; i += TQ) {
            int c = i / TQ, j = i % TQ;
            smc[j * CP + c] = fb[(size_t)c * NP + m0 + j];
        }
        smxx[threadIdx.x] = xx[b * NP + m0 + threadIdx.x];
        __syncthreads();

        for (int j = 0; j < TQ; j += 2) {
            const float* c0 = &smc[j * CP];
            const float* c1 = &smc[(j + 1) * CP];
            float d0 = 2.f * (q0*c0[0] + q1*c0[1] + q2*c0[2]) - smxx[j];
            float d1 = 2.f * (q0*c1[0] + q1*c1[1] + q2*c1[2]) - smxx[j + 1];
            if (d0 > minv) {
                float v = d0; int id = m0 + j;
#pragma unroll
                for (int k = 0; k < KNN; k++) {
                    if (v > vals[k]) {
                        float tv = vals[k]; vals[k] = v; v = tv;
                        int   ti = inds[k]; inds[k] = id; id = ti;
                    }
                }
                minv = vals[KNN - 1];
            }
            if (d1 > minv) {
                float v = d1; int id = m0 + j + 1;
#pragma unroll
                for (int k = 0; k < KNN; k++) {
                    if (v > vals[k]) {
                        float tv = vals[k]; vals[k] = v; v = tv;
                        int   ti = inds[k]; inds[k] = id; id = ti;
                    }
                }
                minv = vals[KNN - 1];
            }
        }
    }
    int* op = idxout + ((size_t)b * NP + n) * KNN;
#pragma unroll
    for (int k = 0; k < KNN; k++) op[k] = inds[k];
}

// ---------------- C=64 knn: f32x2 dots + warm-started gate ----------------
// ft: [b][n][64] (256B rows). prev: previous layer's neighbor idx -> exact
// lower-bound gate tau = min of 20 warm distances (minus margin), guaranteeing
// every true top-20 candidate passes `d > gate` in the scan.
__global__ __launch_bounds__(64)
void knn64_kernel(const float* __restrict__ ft, const float* __restrict__ xx,
                  const int* __restrict__ prev, int* __restrict__ idxout) {
    typedef unsigned long long ull;
    const int TQ = 64;
    const int CP = CH + 4;                      // 272B rows: 16B-aligned, low conflicts
    __shared__ __align__(16) float smc[TQ * CP];
    __shared__ float smxx[TQ];

    int b = blockIdx.y;
    int n = blockIdx.x * TQ + threadIdx.x;
    const float* ftb = ft + (size_t)b * NP * CH;
    const float* xxb = xx + b * NP;

    ull qp[CH / 2];
    {
        const ulonglong2* qs = (const ulonglong2*)(ftb + (size_t)n * CH);
#pragma unroll
        for (int i = 0; i < CH / 4; i++) { ulonglong2 t = qs[i]; qp[2*i] = t.x; qp[2*i+1] = t.y; }
    }

    float vals[KNN];
    int   inds[KNN];
#pragma unroll
    for (int k = 0; k < KNN; k++) { vals[k] = -3.4e38f; inds[k] = 0; }

    // ---- warm start: tau = min over prev-layer neighbors' distances ----
    float tau = 3.4e38f;
    {
        const int* pi = prev + ((size_t)b * NP + n) * KNN;
#pragma unroll 4
        for (int k = 0; k < KNN; k++) {
            int m = pi[k];
            const ulonglong2* cs = (const ulonglong2*)(ftb + (size_t)m * CH);
            ull a0 = 0ull, a1 = 0ull;
#pragma unroll
            for (int i = 0; i < CH / 4; i++) {
                ulonglong2 t = cs[i];
                FMA_F32X2(a0, qp[2*i],   t.x, a0);
                FMA_F32X2(a1, qp[2*i+1], t.y, a1);
            }
            float d = 2.f * (f32x2_hsum(a0) + f32x2_hsum(a1)) - xxb[m];
            tau = fminf(tau, d);
        }
    }
    const float gate = tau - fabsf(tau) * 1e-4f - 1e-12f;
    float minv = gate;

    // ---- full scan ----
    for (int m0 = 0; m0 < NP; m0 += TQ) {
        __syncthreads();
        for (int i = threadIdx.x; i < TQ * (CH / 4); i += 64) {
            int j = i >> 4, c4 = i & 15;
            ((float4*)&smc[j * CP])[c4] = ((const float4*)(ftb + (size_t)(m0 + j) * CH))[c4];
        }
        smxx[threadIdx.x] = xxb[m0 + threadIdx.x];
        __syncthreads();

        for (int j = 0; j < TQ; j += 2) {
            const ulonglong2* c0 = (const ulonglong2*)&smc[j * CP];
            const ulonglong2* c1 = (const ulonglong2*)&smc[(j + 1) * CP];
            ull a00 = 0ull, a01 = 0ull, a10 = 0ull, a11 = 0ull;
#pragma unroll
            for (int i = 0; i < CH / 4; i++) {
                ulonglong2 t0 = c0[i], t1 = c1[i];
                FMA_F32X2(a00, qp[2*i],   t0.x, a00);
                FMA_F32X2(a01, qp[2*i+1], t0.y, a01);
                FMA_F32X2(a10, qp[2*i],   t1.x, a10);
                FMA_F32X2(a11, qp[2*i+1], t1.y, a11);
            }
            float d0 = 2.f * (f32x2_hsum(a00) + f32x2_hsum(a01)) - smxx[j];
            float d1 = 2.f * (f32x2_hsum(a10) + f32x2_hsum(a11)) - smxx[j + 1];
            if (d0 > minv) {
                float v = d0; int id = m0 + j;
#pragma unroll
                for (int k = 0; k < KNN; k++) {
                    if (v > vals[k]) {
                        float tv = vals[k]; vals[k] = v; v = tv;
                        int   ti = inds[k]; inds[k] = id; id = ti;
                    }
                }
                minv = fmaxf(vals[KNN - 1], gate);
            }
            if (d1 > minv) {
                float v = d1; int id = m0 + j + 1;
#pragma unroll
                for (int k = 0; k < KNN; k++) {
                    if (v > vals[k]) {
                        float tv = vals[k]; vals[k] = v; v = tv;
                        int   ti = inds[k]; inds[k] = id; id = ti;
                    }
                }
                minv = fmaxf(vals[KNN - 1], gate);
            }
        }
    }
    int* op = idxout + ((size_t)b * NP + n) * KNN;
#pragma unroll
    for (int k = 0; k < KNN; k++) op[k] = inds[k];
}

// ---------------- point transform: A = Wl@f, Bt = (Wr-Wl)@f ----------------
template<int C>
__global__ void pt_kernel(const float* __restrict__ f, const float* __restrict__ Wa,
                          float* __restrict__ A, float* __restrict__ Bt) {
    int i = blockIdx.x * blockDim.x + threadIdx.x;
    if (i >= BB * CH * NP) return;
    int n = i % NP, o = (i / NP) % CH, b = i / (NP * CH);
    const float* fb = f + (size_t)b * C * NP + n;
    const float* w  = Wa + o * 2 * C;
    float a = 0.f, bm = 0.f;
#pragma unroll
    for (int c = 0; c < C; c++) {
        float v = fb[(size_t)c * NP];
        a  += w[c] * v;
        bm += (w[C + c] - w[c]) * v;
    }
    A[i] = a; Bt[i] = bm;
}

// ---------------- y1[bo][n][k] = A[bo][idx[n,k]] + Bt[bo][n] ----------------
__global__ void y1_kernel(const float* __restrict__ A, const float* __restrict__ Bt,
                          const int* __restrict__ idx, float* __restrict__ Y1) {
    __shared__ float sA[NP];                    // 16 KB: full A plane for this (b,o)
    int bo = blockIdx.y;
    int b  = bo / CH;
    for (int i = threadIdx.x; i < NP; i += blockDim.x)
        sA[i] = A[(size_t)bo * NP + i];
    __syncthreads();
    int n0 = blockIdx.x * 512;
    const int*  ib = idx + ((size_t)b * NP + n0) * KNN;
    const float* bt = Bt + (size_t)bo * NP + n0;
    float* y = Y1 + ((size_t)bo * NP + n0) * KNN;
    for (int i = threadIdx.x; i < 512 * KNN; i += blockDim.x) {
        int nl = i / KNN;
        y[i] = sA[ib[i]] + bt[nl];
    }
}

// ---------------- per-channel mean / rstd (fp32, vectorized, one block/channel) ----------------
__global__ __launch_bounds__(256)
void stats_kernel(const float* __restrict__ src, float* __restrict__ stats, int P) {
    int ch = blockIdx.x;
    const float4* p = (const float4*)(src + (size_t)ch * P);
    int P4 = P >> 2;
    float sx = 0.f, sy = 0.f, sz = 0.f, sw = 0.f;
    float qx = 0.f, qy = 0.f, qz = 0.f, qw = 0.f;
    for (int i = threadIdx.x; i < P4; i += 256) {
        float4 v = p[i];
        sx += v.x; sy += v.y; sz += v.z; sw += v.w;
        qx += v.x * v.x; qy += v.y * v.y; qz += v.z * v.z; qw += v.w * v.w;
    }
    float s  = (sx + sy) + (sz + sw);
    float s2 = (qx + qy) + (qz + qw);
    __shared__ float sh[512];
    sh[threadIdx.x] = s; sh[256 + threadIdx.x] = s2;
    __syncthreads();
    for (int st = 128; st > 0; st >>= 1) {
        if (threadIdx.x < st) {
            sh[threadIdx.x]       += sh[threadIdx.x + st];
            sh[256 + threadIdx.x] += sh[256 + threadIdx.x + st];
        }
        __syncthreads();
    }
    if (threadIdx.x == 0) {
        float m   = sh[0] / (float)P;
        float var = sh[256] / (float)P - m * m;
        stats[ch * 2]     = m;
        stats[ch * 2 + 1] = rsqrtf(var + CEPS);
    }
}

// ---------------- conv2: y2 = Wb @ lrelu(inorm(y1)), 2 points/thread ----------------
__global__ __launch_bounds__(128)
void conv2_kernel(const float* __restrict__ Y1, const float* __restrict__ Wb,
                  const float* __restrict__ stats, float* __restrict__ Y2) {
    const int P = NP * KNN;
    __shared__ float sWt[CH * CH];      // transposed: [c][o]
    __shared__ float sm[CH], sr[CH];
    int b = blockIdx.y;
    for (int i = threadIdx.x; i < CH * CH; i += 128) {
        int c = i >> 6, o = i & 63;
        sWt[c * CH + o] = Wb[o * CH + c];
    }
    if (threadIdx.x < CH) {
        sm[threadIdx.x] = stats[(b * CH + threadIdx.x) * 2];
        sr[threadIdx.x] = stats[(b * CH + threadIdx.x) * 2 + 1];
    }
    __syncthreads();
    int p0 = blockIdx.x * 256 + threadIdx.x;
    int p1 = p0 + 128;
    float acc0[CH], acc1[CH];
#pragma unroll
    for (int o = 0; o < CH; o++) { acc0[o] = 0.f; acc1[o] = 0.f; }
    const float* y1 = Y1 + (size_t)b * CH * P;
#pragma unroll 2
    for (int c = 0; c < CH; c++) {
        float v0 = y1[(size_t)c * P + p0];
        float v1 = y1[(size_t)c * P + p1];
        float m = sm[c], r = sr[c];
        v0 = (v0 - m) * r; v0 = v0 > 0.f ? v0 : 0.2f * v0;
        v1 = (v1 - m) * r; v1 = v1 > 0.f ? v1 : 0.2f * v1;
        const float4* w = (const float4*)&sWt[c * CH];
#pragma unroll
        for (int o4 = 0; o4 < 16; o4++) {
            float4 w4 = w[o4];
            acc0[4*o4+0] += w4.x * v0; acc1[4*o4+0] += w4.x * v1;
            acc0[4*o4+1] += w4.y * v0; acc1[4*o4+1] += w4.y * v1;
            acc0[4*o4+2] += w4.z * v0; acc1[4*o4+2] += w4.z * v1;
            acc0[4*o4+3] += w4.w * v0; acc1[4*o4+3] += w4.w * v1;
        }
    }
    float* y2 = Y2 + (size_t)b * CH * P;
#pragma unroll
    for (int o = 0; o < CH; o++) {
        y2[(size_t)o * P + p0] = acc0[o];
        y2[(size_t)o * P + p1] = acc1[o];
    }
}

// ---------------- max over K of lrelu(inorm(y2)) ----------------
__global__ void maxk_kernel(const float* __restrict__ Y2, const float* __restrict__ stats,
                            float* __restrict__ xout) {
    int i = blockIdx.x * blockDim.x + threadIdx.x;   // over B*CH*NP
    if (i >= BB * CH * NP) return;
    int bo = i / NP;
    float m = stats[bo * 2], r = stats[bo * 2 + 1];
    const float4* y = (const float4*)(Y2 + (size_t)i * KNN);
    float mx = -3.4e38f;
#pragma unroll
    for (int k4 = 0; k4 < 5; k4++) {
        float4 v = y[k4];
        mx = fmaxf(mx, fmaxf(fmaxf(v.x, v.y), fmaxf(v.z, v.w)));
    }
    float v = (mx - m) * r;          // max commutes with the monotone affine map (r>0)
    v = v > 0.f ? v : 0.2f * v;
    xout[i] = v;
}

// ---------------- final GEMM: Y[b, o, n] = Ws[o, :] @ concat(x1,x2,x3)[b, :, n] ----------------
__global__ __launch_bounds__(128)
void fgemm_kernel(const float* __restrict__ x1, const float* __restrict__ x2,
                  const float* __restrict__ x3, const float* __restrict__ Ws,
                  float* __restrict__ Y) {
    __shared__ float sWt[192 * 64];                // transposed [c][o], 48 KB
    int b  = blockIdx.z;
    int o0 = blockIdx.y * 64;
    int n0 = blockIdx.x * 256 + threadIdx.x;
    int n1 = n0 + 128;
    for (int i = threadIdx.x; i < 192 * 64; i += 128) {
        int c = i >> 6, o = i & 63;
        sWt[c * 64 + o] = Ws[(size_t)(o0 + o) * 192 + c];
    }
    __syncthreads();
    float acc0[64], acc1[64];
#pragma unroll
    for (int o = 0; o < 64; o++) { acc0[o] = 0.f; acc1[o] = 0.f; }
    const float* srcs[3] = { x1 + (size_t)b * CH * NP,
                             x2 + (size_t)b * CH * NP,
                             x3 + (size_t)b * CH * NP };
    for (int g = 0; g < 3; g++) {
        const float* s = srcs[g];
#pragma unroll 2
        for (int c = 0; c < 64; c++) {
            float v0 = s[(size_t)c * NP + n0];
            float v1 = s[(size_t)c * NP + n1];
            const float4* w = (const float4*)&sWt[(g * 64 + c) * 64];
#pragma unroll
            for (int o4 = 0; o4 < 16; o4++) {
                float4 w4 = w[o4];
                acc0[4*o4+0] += w4.x * v0; acc1[4*o4+0] += w4.x * v1;
                acc0[4*o4+1] += w4.y * v0; acc1[4*o4+1] += w4.y * v1;
                acc0[4*o4+2] += w4.z * v0; acc1[4*o4+2] += w4.z * v1;
                acc0[4*o4+3] += w4.w * v0; acc1[4*o4+3] += w4.w * v1;
            }
        }
    }
    float* y = Y + ((size_t)b * 1024 + o0) * NP;
#pragma unroll
    for (int o = 0; o < 64; o++) {
        y[(size_t)o * NP + n0] = acc0[o];
        y[(size_t)o * NP + n1] = acc1[o];
    }
}

// ---------------- global max pool of lrelu(inorm(Y)) ----------------
__global__ void pool_kernel(const float* __restrict__ Y, const float* __restrict__ stats,
                            float* __restrict__ pool) {
    int ch = blockIdx.x;            // b*1024 + o
    float m = stats[ch * 2], r = stats[ch * 2 + 1];
    const float4* y = (const float4*)(Y + (size_t)ch * NP);
    float mx = -3.4e38f;
    for (int i = threadIdx.x; i < NP / 4; i += 128) {
        float4 v = y[i];
        mx = fmaxf(mx, fmaxf(fmaxf(v.x, v.y), fmaxf(v.z, v.w)));
    }
    __shared__ float sh[128];
    sh[threadIdx.x] = mx; __syncthreads();
    for (int st = 64; st > 0; st >>= 1) {
        if (threadIdx.x < st) sh[threadIdx.x] = fmaxf(sh[threadIdx.x], sh[threadIdx.x + st]);
        __syncthreads();
    }
    if (threadIdx.x == 0) {
        float v = (sh[0] - m) * r;   // max commutes with monotone affine map (r>0)
        v = v > 0.f ? v : 0.2f * v;
        pool[ch] = v;
    }
}

// ---------------- assemble output: [pool bcast | x1 | x2 | x3] ----------------
__global__ void out_kernel(const float* __restrict__ pool, const float* __restrict__ x1,
                           const float* __restrict__ x2, const float* __restrict__ x3,
                           float* __restrict__ out) {
    size_t i = (size_t)blockIdx.x * blockDim.x + threadIdx.x;
    const size_t total = (size_t)BB * 1216 * NP;
    if (i >= total) return;
    int n  = (int)(i % NP);
    int ch = (int)((i / NP) % 1216);
    int b  = (int)(i / ((size_t)NP * 1216));
    float v;
    if (ch < 1024) {
        v = pool[b * 1024 + ch];
    } else {
        int c2 = ch - 1024;
        const float* s = (c2 < 64) ? x1 : (c2 < 128 ? x2 : x3);
        v = s[((size_t)b * CH + (c2 & 63)) * NP + n];
    }
    out[i] = v;
}

// ---------------- conv tail shared by all layers ----------------
static void run_conv_tail(const float* Wb, const int* idxp, float* Ap, float* Btp,
                          float* Y1p, float* Y2p, float* stp, float* xout) {
    y1_kernel<<<dim3(NP / 512, BB * CH), 256>>>(Ap, Btp, idxp, Y1p);
    stats_kernel<<<BB * CH, 256>>>(Y1p, stp, NP * KNN);
    conv2_kernel<<<dim3(NP * KNN / 256, BB), 128>>>(Y1p, Wb, stp, Y2p);
    stats_kernel<<<BB * CH, 256>>>(Y2p, stp, NP * KNN);
    maxk_kernel<<<(BB * CH * NP + 255) / 256, 256>>>(Y2p, stp, xout);
}

extern "C" void kernel_launch(void* const* d_in, const int* in_sizes, int n_in,
                              void* d_out, int out_size) {
    const float* x   = (const float*)d_in[0];
    const float* W0a = (const float*)d_in[1];
    const float* W0b = (const float*)d_in[2];
    const float* W1a = (const float*)d_in[3];
    const float* W1b = (const float*)d_in[4];
    const float* W2a = (const float*)d_in[5];
    const float* W2b = (const float*)d_in[6];
    const float* Ws  = (const float*)d_in[7];
    float* out = (float*)d_out;

    float *xxp, *ftp, *Ap, *Btp, *Y1p, *Y2p, *x1p, *x2p, *x3p, *stp, *Yp, *poolp;
    int *idxAp, *idxBp;
    cudaGetSymbolAddress((void**)&xxp,   g_xx);
    cudaGetSymbolAddress((void**)&idxAp, g_idxA);
    cudaGetSymbolAddress((void**)&idxBp, g_idxB);
    cudaGetSymbolAddress((void**)&ftp,   g_ft);
    cudaGetSymbolAddress((void**)&Ap,    g_A);
    cudaGetSymbolAddress((void**)&Btp,   g_Bt);
    cudaGetSymbolAddress((void**)&Y1p,   g_Y1);
    cudaGetSymbolAddress((void**)&Y2p,   g_Y2);
    cudaGetSymbolAddress((void**)&x1p,   g_x1);
    cudaGetSymbolAddress((void**)&x2p,   g_x2);
    cudaGetSymbolAddress((void**)&x3p,   g_x3);
    cudaGetSymbolAddress((void**)&stp,   g_st);
    cudaGetSymbolAddress((void**)&Yp,    g_Y);
    cudaGetSymbolAddress((void**)&poolp, g_pool);

    // ---- layer 0 (C=3): knn on raw coords -> idxA ----
    xx_kernel<3><<<(BB * NP + 255) / 256, 256>>>(x, xxp);
    knn3_kernel<<<dim3(NP / 128, BB), 128>>>(x, xxp, idxAp);
    pt_kernel<3><<<(BB * CH * NP + 255) / 256, 256>>>(x, W0a, Ap, Btp);
    run_conv_tail(W0b, idxAp, Ap, Btp, Y1p, Y2p, stp, x1p);

    // ---- layer 1 (C=64): knn on x1, warm from idxA -> idxB ----
    xx_kernel<CH><<<(BB * NP + 255) / 256, 256>>>(x1p, xxp);
    transpose_kernel<<<dim3(NP / 32, CH / 32, BB), dim3(32, 8)>>>(x1p, ftp);
    knn64_kernel<<<dim3(NP / 64, BB), 64>>>(ftp, xxp, idxAp, idxBp);
    pt_kernel<CH><<<(BB * CH * NP + 255) / 256, 256>>>(x1p, W1a, Ap, Btp);
    run_conv_tail(W1b, idxBp, Ap, Btp, Y1p, Y2p, stp, x2p);

    // ---- layer 2 (C=64): knn on x2, warm from idxB -> idxA ----
    xx_kernel<CH><<<(BB * NP + 255) / 256, 256>>>(x2p, xxp);
    transpose_kernel<<<dim3(NP / 32, CH / 32, BB), dim3(32, 8)>>>(x2p, ftp);
    knn64_kernel<<<dim3(NP / 64, BB), 64>>>(ftp, xxp, idxBp, idxAp);
    pt_kernel<CH><<<(BB * CH * NP + 255) / 256, 256>>>(x2p, W2a, Ap, Btp);
    run_conv_tail(W2b, idxAp, Ap, Btp, Y1p, Y2p, stp, x3p);

    // ---- head ----
    fgemm_kernel<<<dim3(NP / 256, 1024 / 64, BB), 128>>>(x1p, x2p, x3p, Ws, Yp);
    stats_kernel<<<BB * 1024, 256>>>(Yp, stp, NP);
    pool_kernel<<<BB * 1024, 128>>>(Yp, stp, poolp);

    const size_t total = (size_t)BB * 1216 * NP;
    out_kernel<<<(unsigned)((total + 255) / 256), 256>>>(poolp, x1p, x2p, x3p, out);
}